// round 11
// baseline (speedup 1.0000x reference)
#include <cuda_runtime.h>
#include <cuda_bf16.h>
#include <math.h>
#include <stdint.h>

// Shapes: B=4, N=256, F=64, H=256, A=16, T=3
#define Bn 4
#define Nn 256
#define Fn 64
#define Hn 256
#define An 16
#define Tn 3
#define BN 1024
#define NC 1280
#define STAGES 3
#define AS_W 132      // duplicated A row: 128 floats + 4 pad

typedef unsigned long long u64;

// ---------------- scratch (device globals) -----------------------------------
__device__ float d_XT  [Fn*BN];      // X^T        [64][1024]
__device__ float d_tT  [Hn*BN];      // pre-hidden^T
__device__ float d_hT  [Hn*BN];      // h^T
__device__ float d_aT  [Hn*BN];      // agg0^T
__device__ float d_M2T [Hn*Hn];      // msg_W2^T
__device__ float d_big2[BN*512];     // [hi+b1 | hj] row-major
__device__ float d_ghT [768*BN];     // gh^T (+bhh)
__device__ float d_giT [768*BN];     // gi^T
__device__ float d_deg [BN];
__device__ float d_Wc  [Hn*768];     // msg_W2 @ gru_Wih (row-major)
__device__ float d_bc  [768];        // msg_b2 @ gru_Wih
__device__ float d_Wcat[Hn*NC];      // [W1_i | W1_j | Whh] row-major
__device__ float d_bcat[NC];

// ---------------- helpers ------------------------------------------------------
#define FMA2(acc, a, b) \
    asm("fma.rn.f32x2 %0, %1, %2, %0;" : "+l"(acc) : "l"(a), "l"(b))
#define UNPACK2(lo, hi, s) \
    asm("mov.b64 {%0, %1}, %2;" : "=f"(lo), "=f"(hi) : "l"(s))

__device__ __forceinline__ void cpa16(void* s, const void* g) {
    uint32_t sa = (uint32_t)__cvta_generic_to_shared(s);
    asm volatile("cp.async.ca.shared.global [%0], [%1], 16;" :: "r"(sa), "l"(g));
}

// ---------------- pipelined fp32 GEMM -----------------------------------------
// C = f(A@B + bias + rowS*colV), A TRANSPOSED At[k][m] (ld ldaT), B row-major.
// Tile 64x64, 128 thr, FFMA2, 3-stage pipeline, K-chunks of 16 (K>=32, mult 16).
// A stored DUPLICATED in smem ({a,a} pairs) -> FMA2 operands direct from LDS.
// Block cols < splitCol -> Crow[r][c] (ld ldC); else CtrT[(c-splitCol)][r] (ld ldT).
__global__ void __launch_bounds__(128)
gemmT(const float* __restrict__ At, int ldaT,
      const float* __restrict__ Bm, int N, int K,
      const float* __restrict__ bias,
      const float* __restrict__ rowS, const float* __restrict__ colV,
      float* __restrict__ Crow, int ldC, int splitCol,
      float* __restrict__ CtrT, int ldT, int doRelu)
{
    __shared__ __align__(16) float As[STAGES][16][AS_W];   // duplicated pairs
    __shared__ __align__(16) float Bs[STAGES][16][64];

    int tid = threadIdx.x;
    int l = tid & 31, w = tid >> 5;
    int wm = w >> 1, wn = w & 1;
    int rg = l >> 2, cg = l & 3;
    int row0 = blockIdx.y * 64, col0 = blockIdx.x * 64;

    int lk = tid >> 4, lseg = (tid & 15) << 2;   // loader: k row (0..7), 16B seg
    const float* Abase = At + row0 + lseg;
    const float* Bbase = Bm + col0 + lseg;

#define STSDUP(st, row, v) do {                                   \
        float4 _d0 = {v.x, v.x, v.y, v.y};                        \
        float4 _d1 = {v.z, v.z, v.w, v.w};                        \
        *(float4*)&As[st][row][2*lseg]     = _d0;                 \
        *(float4*)&As[st][row][2*lseg + 4] = _d1;                 \
    } while (0)

    u64 acc[4][4];
    #pragma unroll
    for (int i = 0; i < 4; i++)
        #pragma unroll
        for (int j = 0; j < 4; j++) acc[i][j] = 0ull;

    int nch = K >> 4;
    // prologue: A chunks 0,1 via LDG; B chunks 0,1 via cp.async
    float4 aA0 = *(const float4*)(Abase + (size_t)(lk     ) * ldaT);
    float4 aB0 = *(const float4*)(Abase + (size_t)(lk +  8) * ldaT);
    float4 aA1 = *(const float4*)(Abase + (size_t)(lk + 16) * ldaT);
    float4 aB1 = *(const float4*)(Abase + (size_t)(lk + 24) * ldaT);
    cpa16(&Bs[0][lk][lseg],     Bbase + (size_t)(lk    ) * N);
    cpa16(&Bs[0][lk + 8][lseg], Bbase + (size_t)(lk + 8) * N);
    asm volatile("cp.async.commit_group;");
    cpa16(&Bs[1][lk][lseg],     Bbase + (size_t)(lk + 16) * N);
    cpa16(&Bs[1][lk + 8][lseg], Bbase + (size_t)(lk + 24) * N);
    asm volatile("cp.async.commit_group;");
    STSDUP(0, lk,     aA0); STSDUP(0, lk + 8, aB0);
    STSDUP(1, lk,     aA1); STSDUP(1, lk + 8, aB1);

    int mrow = wm * 32 + rg * 4, nc0 = wn * 32 + cg * 4;
    int base2 = 2 * mrow;
    int s = 0;
    float4 pA, pB;
    for (int ch = 0; ch < nch; ch++) {
        if (ch < nch - 1) asm volatile("cp.async.wait_group 1;");
        else              asm volatile("cp.async.wait_group 0;");
        __syncthreads();
        int s2 = s + 2; if (s2 >= STAGES) s2 -= STAGES;

        if (ch + 2 < nch) {
            int kc = (ch + 2) << 4;
            pA = *(const float4*)(Abase + (size_t)(kc + lk    ) * ldaT);
            pB = *(const float4*)(Abase + (size_t)(kc + lk + 8) * ldaT);
            cpa16(&Bs[s2][lk][lseg],     Bbase + (size_t)(kc + lk    ) * N);
            cpa16(&Bs[s2][lk + 8][lseg], Bbase + (size_t)(kc + lk + 8) * N);
            asm volatile("cp.async.commit_group;");
        }

        // 16 k-steps, register-prefetched one step ahead
        ulonglong2 xa = *(ulonglong2*)&As[s][0][base2];
        ulonglong2 xb = *(ulonglong2*)&As[s][0][base2 + 4];
        ulonglong2 y0 = *(ulonglong2*)&Bs[s][0][nc0];
        ulonglong2 y1 = *(ulonglong2*)&Bs[s][0][nc0 + 16];
        #pragma unroll
        for (int k = 0; k < 16; k++) {
            ulonglong2 na, nb, n0, n1;
            if (k < 15) {
                na = *(ulonglong2*)&As[s][k + 1][base2];
                nb = *(ulonglong2*)&As[s][k + 1][base2 + 4];
                n0 = *(ulonglong2*)&Bs[s][k + 1][nc0];
                n1 = *(ulonglong2*)&Bs[s][k + 1][nc0 + 16];
            }
            FMA2(acc[0][0], xa.x, y0.x); FMA2(acc[0][1], xa.x, y0.y);
            FMA2(acc[0][2], xa.x, y1.x); FMA2(acc[0][3], xa.x, y1.y);
            FMA2(acc[1][0], xa.y, y0.x); FMA2(acc[1][1], xa.y, y0.y);
            FMA2(acc[1][2], xa.y, y1.x); FMA2(acc[1][3], xa.y, y1.y);
            FMA2(acc[2][0], xb.x, y0.x); FMA2(acc[2][1], xb.x, y0.y);
            FMA2(acc[2][2], xb.x, y1.x); FMA2(acc[2][3], xb.x, y1.y);
            FMA2(acc[3][0], xb.y, y0.x); FMA2(acc[3][1], xb.y, y0.y);
            FMA2(acc[3][2], xb.y, y1.x); FMA2(acc[3][3], xb.y, y1.y);
            xa = na; xb = nb; y0 = n0; y1 = n1;
        }

        if (ch + 2 < nch) {               // STS after compute; LDG has landed
            STSDUP(s2, lk,     pA);
            STSDUP(s2, lk + 8, pB);
        }
        s++; if (s >= STAGES) s = 0;
    }

    // epilogue
    float vv[4][8];
    #pragma unroll
    for (int i = 0; i < 4; i++) {
        UNPACK2(vv[i][0], vv[i][1], acc[i][0]);
        UNPACK2(vv[i][2], vv[i][3], acc[i][1]);
        UNPACK2(vv[i][4], vv[i][5], acc[i][2]);
        UNPACK2(vv[i][6], vv[i][7], acc[i][3]);
    }
    const int cofs[8] = {0, 1, 2, 3, 16, 17, 18, 19};
    int c0 = col0 + nc0;
    float bj[8], cvj[8];
    #pragma unroll
    for (int j = 0; j < 8; j++) {
        int c = c0 + cofs[j];
        bj[j]  = bias ? bias[c] : 0.f;
        cvj[j] = rowS ? colV[c] : 0.f;
    }
    #pragma unroll
    for (int i = 0; i < 4; i++) {
        int r = row0 + mrow + i;
        float rs = rowS ? rowS[r] : 0.f;
        #pragma unroll
        for (int j = 0; j < 8; j++) {
            float v = vv[i][j] + bj[j] + rs * cvj[j];
            if (doRelu) v = fmaxf(v, 0.f);
            vv[i][j] = v;
        }
    }
    if (col0 < splitCol) {
        #pragma unroll
        for (int i = 0; i < 4; i++) {
            int r = row0 + mrow + i;
            float4 o0 = {vv[i][0], vv[i][1], vv[i][2], vv[i][3]};
            float4 o1 = {vv[i][4], vv[i][5], vv[i][6], vv[i][7]};
            *(float4*)(Crow + (size_t)r * ldC + c0)      = o0;
            *(float4*)(Crow + (size_t)r * ldC + c0 + 16) = o1;
        }
    } else {
        int rbase = row0 + mrow;
        #pragma unroll
        for (int j = 0; j < 8; j++) {
            float4 o = {vv[0][j], vv[1][j], vv[2][j], vv[3][j]};
            *(float4*)(CtrT + (size_t)(c0 + cofs[j] - splitCol) * ldT + rbase) = o;
        }
    }
#undef STSDUP
}

// ---------------- prep: transposes + Wcat/bcat + bc ---------------------------
__global__ void prep(const float* __restrict__ X, const float* __restrict__ msgW2,
                     const float* __restrict__ msgW1, const float* __restrict__ Whh,
                     const float* __restrict__ msgb1, const float* __restrict__ bhh,
                     const float* __restrict__ msgb2, const float* __restrict__ Wih,
                     float* __restrict__ XT, float* __restrict__ M2T,
                     float* __restrict__ Wcat, float* __restrict__ bcat,
                     float* __restrict__ bc)
{
    int blk = blockIdx.x, t = threadIdx.x;
    if (blk < 256) {                     // XT[k][m] = X[m][k]
        int i = blk * 256 + t;
        int k = i >> 10, m = i & 1023;
        XT[i] = X[(size_t)m * Fn + k];
    } else if (blk < 512) {              // M2T[k][m] = msg_W2[m][k]
        int i = (blk - 256) * 256 + t;
        int k = i >> 8, m = i & 255;
        M2T[i] = msgW2[(size_t)m * Hn + k];
    } else if (blk < 1792) {             // Wcat[k][n]
        int i = (blk - 512) * 256 + t;
        int k = i / NC, n = i % NC;
        float v;
        if (n < 256)      v = msgW1[(size_t)k * Hn + n];
        else if (n < 512) v = msgW1[(size_t)(256 + k) * Hn + (n - 256)];
        else              v = Whh[(size_t)k * 768 + (n - 512)];
        Wcat[i] = v;
        if (i < NC)
            bcat[i] = i < 256 ? msgb1[i] : (i < 512 ? 0.f : bhh[i - 512]);
    } else {                             // bc = msg_b2 @ gru_Wih (warp/output)
        int warp = (blk - 1792) * 8 + (t >> 5);
        int lane = t & 31;
        float s = 0.f;
        for (int k = lane; k < Hn; k += 32)
            s += msgb2[k] * Wih[(size_t)k * 768 + warp];
        #pragma unroll
        for (int o = 16; o; o >>= 1) s += __shfl_xor_sync(0xffffffffu, s, o);
        if (lane == 0) bc[warp] = s;
    }
}

// ---------------- E-aggregation -----------------------------------------------
#define IT 8
__global__ void eagg(const float* __restrict__ big2, const int* __restrict__ adj,
                     float* __restrict__ aT, float* __restrict__ deg)
{
    int b  = blockIdx.y;
    int i0 = blockIdx.x * IT;
    int h  = threadIdx.x;

    __shared__ float adjf[Nn][IT];

    float hir[IT], acc[IT];
    #pragma unroll
    for (int t = 0; t < IT; t++) {
        adjf[h][t] = (float)adj[((size_t)(b * Nn + i0 + t)) * Nn + h];
        hir[t] = big2[((size_t)(b * Nn + i0 + t)) * 512 + h];
        acc[t] = 0.f;
    }
    __syncthreads();

    const float* hjb = big2 + (size_t)b * Nn * 512 + 256;
    #pragma unroll 2
    for (int j = 0; j < Nn; j++) {
        float hjv = hjb[(size_t)j * 512 + h];
        float4 a04 = *(float4*)&adjf[j][0];
        float4 a47 = *(float4*)&adjf[j][4];
        acc[0] += a04.x * fmaxf(hir[0] + hjv, 0.f);
        acc[1] += a04.y * fmaxf(hir[1] + hjv, 0.f);
        acc[2] += a04.z * fmaxf(hir[2] + hjv, 0.f);
        acc[3] += a04.w * fmaxf(hir[3] + hjv, 0.f);
        acc[4] += a47.x * fmaxf(hir[4] + hjv, 0.f);
        acc[5] += a47.y * fmaxf(hir[5] + hjv, 0.f);
        acc[6] += a47.z * fmaxf(hir[6] + hjv, 0.f);
        acc[7] += a47.w * fmaxf(hir[7] + hjv, 0.f);
    }

    #pragma unroll
    for (int t = 0; t < IT; t++)
        aT[(size_t)h * BN + b * Nn + i0 + t] = acc[t];

    if (h < IT) {
        float s = 0.f;
        for (int j = 0; j < Nn; j++) s += adjf[j][h];
        deg[b * Nn + i0 + h] = s;
    }
}

// ---------------- GRU elementwise (coalesced on transposed layouts) -----------
__global__ void gru(const float* __restrict__ giT, const float* __restrict__ ghT,
                    float* __restrict__ hT)
{
    int id = blockIdx.x * 256 + threadIdx.x;   // over Hn*BN, m fastest
    int m = id & 1023, c = id >> 10;
    float ir = giT[(size_t)c * BN + m];
    float iz = giT[(size_t)(c + 256) * BN + m];
    float in = giT[(size_t)(c + 512) * BN + m];
    float hr = ghT[(size_t)c * BN + m];
    float hz = ghT[(size_t)(c + 256) * BN + m];
    float hn = ghT[(size_t)(c + 512) * BN + m];
    float r = 1.f / (1.f + __expf(-(ir + hr)));
    float z = 1.f / (1.f + __expf(-(iz + hz)));
    float n = tanhf(in + r * hn);
    hT[id] = (1.f - z) * n + z * hT[id];
}

// ---------------- readout ------------------------------------------------------
__global__ void readout(const float* __restrict__ hT,
                        const float* __restrict__ W1, const float* __restrict__ b1,
                        const float* __restrict__ W2, const float* __restrict__ b2,
                        float* __restrict__ out)
{
    __shared__ float gsh[Hn];
    __shared__ float hsh[Hn];
    int b = blockIdx.x, t = threadIdx.x;

    float s = 0.f;
    const float* hrow = hT + (size_t)t * BN + b * Nn;
    #pragma unroll 4
    for (int i = 0; i < Nn; i++) s += hrow[i];
    gsh[t] = s;
    __syncthreads();

    float s2 = b1[t];
    for (int k = 0; k < Hn; k++) s2 += gsh[k] * W1[(size_t)k * Hn + t];
    hsh[t] = fmaxf(s2, 0.f);
    __syncthreads();

    if (t < An) {
        float s3 = b2[t];
        for (int k = 0; k < Hn; k++) s3 += hsh[k] * W2[(size_t)k * An + t];
        out[b * An + t] = s3;
    }
}

// ---------------- host launch ---------------------------------------------------
extern "C" void kernel_launch(void* const* d_in, const int* in_sizes, int n_in,
                              void* d_out, int out_size)
{
    const float* X       = (const float*)d_in[0];
    const int*   adj     = (const int*)  d_in[1];
    const float* pre_W1  = (const float*)d_in[2];
    const float* pre_b1  = (const float*)d_in[3];
    const float* pre_W2  = (const float*)d_in[4];
    const float* pre_b2  = (const float*)d_in[5];
    const float* msg_W1  = (const float*)d_in[6];
    const float* msg_b1  = (const float*)d_in[7];
    const float* msg_W2  = (const float*)d_in[8];
    const float* msg_b2  = (const float*)d_in[9];
    const float* gru_Wih = (const float*)d_in[10];
    const float* gru_Whh = (const float*)d_in[11];
    const float* gru_bih = (const float*)d_in[12];
    const float* gru_bhh = (const float*)d_in[13];
    const float* ro_W1   = (const float*)d_in[14];
    const float* ro_b1   = (const float*)d_in[15];
    const float* ro_W2   = (const float*)d_in[16];
    const float* ro_b2   = (const float*)d_in[17];

    float *XT,*tT,*hT,*aT,*M2T,*big2,*ghT,*giT,*deg,*Wc,*bc,*Wcat,*bcat;
    cudaGetSymbolAddress((void**)&XT,  d_XT);
    cudaGetSymbolAddress((void**)&tT,  d_tT);
    cudaGetSymbolAddress((void**)&hT,  d_hT);
    cudaGetSymbolAddress((void**)&aT,  d_aT);
    cudaGetSymbolAddress((void**)&M2T, d_M2T);
    cudaGetSymbolAddress((void**)&big2,d_big2);
    cudaGetSymbolAddress((void**)&ghT, d_ghT);
    cudaGetSymbolAddress((void**)&giT, d_giT);
    cudaGetSymbolAddress((void**)&deg, d_deg);
    cudaGetSymbolAddress((void**)&Wc,  d_Wc);
    cudaGetSymbolAddress((void**)&bc,  d_bc);
    cudaGetSymbolAddress((void**)&Wcat,d_Wcat);
    cudaGetSymbolAddress((void**)&bcat,d_bcat);

    // prep: XT, M2T, Wcat, bcat, bc
    prep<<<1888, 256>>>(X, msg_W2, msg_W1, gru_Whh, msg_b1, gru_bhh, msg_b2, gru_Wih,
                        XT, M2T, Wcat, bcat, bc);

    // Wc = msg_W2 @ gru_Wih (row-major out)
    gemmT<<<dim3(12, 4), 128>>>(M2T, Hn, gru_Wih, 768, Hn,
                                nullptr, nullptr, nullptr,
                                Wc, 768, 768, nullptr, 0, 0);

    // pre-MLP: tT = relu(X@W1+b1)^T ; hT = (t@W2+b2)^T
    gemmT<<<dim3(4, 16), 128>>>(XT, BN, pre_W1, Hn, Fn,
                                pre_b1, nullptr, nullptr,
                                nullptr, 0, 0, tT, BN, 1);
    gemmT<<<dim3(4, 16), 128>>>(tT, BN, pre_W2, Hn, Hn,
                                pre_b2, nullptr, nullptr,
                                nullptr, 0, 0, hT, BN, 0);

    for (int it = 0; it < Tn; it++) {
        // [hi+b1 | hj] -> big2 (row-major), gh+bhh -> ghT (transposed)
        gemmT<<<dim3(20, 16), 128>>>(hT, BN, Wcat, NC, Hn,
                                     bcat, nullptr, nullptr,
                                     big2, 512, 512, ghT, BN, 0);
        eagg<<<dim3(Nn / IT, Bn), 256>>>(big2, adj, aT, deg);
        // giT = (agg0 @ Wc + deg*bc + bih)^T
        gemmT<<<dim3(12, 16), 128>>>(aT, BN, Wc, 768, Hn,
                                     gru_bih, deg, bc,
                                     nullptr, 0, 0, giT, BN, 0);
        gru<<<Hn * BN / 256, 256>>>(giT, ghT, hT);
    }

    readout<<<Bn, 256>>>(hT, ro_W1, ro_b1, ro_W2, ro_b2, (float*)d_out);
}

// round 12
// speedup vs baseline: 1.0121x; 1.0121x over previous
#include <cuda_runtime.h>
#include <math.h>
#include <stdint.h>

// Shapes: B=4, N=256, F=64, H=256, A=16, T=3
#define Bn 4
#define Nn 256
#define Fn 64
#define Hn 256
#define An 16
#define Tn 3
#define BN 1024
#define NC 1280
#define G 296                 // persistent grid: 2 CTAs/SM x 148 SMs

typedef unsigned long long u64;

// ---------------- scratch (device globals) -----------------------------------
__device__ float d_XT  [Fn*BN];
__device__ float d_tT  [Hn*BN];
__device__ float d_hT  [Hn*BN];
__device__ float d_aT  [Hn*BN];
__device__ float d_M2T [Hn*Hn];
__device__ float d_big2[BN*512];
__device__ float d_ghT [768*BN];
__device__ float d_giT [768*BN];
__device__ float d_deg [BN];
__device__ float d_Wc  [Hn*768];
__device__ float d_bc  [768];
__device__ float d_Wcat[Hn*NC];
__device__ float d_bcat[NC];
__device__ unsigned g_cnt;
__device__ volatile unsigned g_gen;

// ---------------- helpers ------------------------------------------------------
#define FMA2(acc, a, b) \
    asm("fma.rn.f32x2 %0, %1, %2, %0;" : "+l"(acc) : "l"(a), "l"(b))
#define PACKDUP(d, s) \
    asm("mov.b64 %0, {%1, %1};" : "=l"(d) : "f"(s))
#define UNPACK2(lo, hi, s) \
    asm("mov.b64 {%0, %1}, %2;" : "=f"(lo), "=f"(hi) : "l"(s))

__device__ __forceinline__ void cpacg(uint32_t s, const void* g) {
    asm volatile("cp.async.cg.shared.global [%0], [%1], 16;" :: "r"(s), "l"(g));
}

// grid-wide barrier: all G blocks must be resident (guaranteed by launch_bounds)
__device__ __forceinline__ void gridbar() {
    __syncthreads();
    if (threadIdx.x == 0) {
        unsigned gen = g_gen;
        __threadfence();                       // release: my writes visible
        if (atomicAdd(&g_cnt, 1u) == G - 1u) {
            g_cnt = 0u;
            __threadfence();
            g_gen = gen + 1u;                  // release all waiters
        } else {
            while (g_gen == gen) { __nanosleep(32); }
            __threadfence();                   // acquire
        }
    }
    __syncthreads();
}

// ---------------- one 64x64 GEMM tile (256 thr, cp.async double-buffer, FFMA2)
// C = f(A@B + bias + rowS*colV); A TRANSPOSED At[k][m] (ld ldaT); B row-major KxN.
// col0 < splitCol -> Crow[r][c] (ld ldC) ; else CtrT[(c-splitCol)][r] (ld ldT).
// smraw layout: As[2][16][68] (8704B) | Bs[2][16][64] (8192B)
__device__ __noinline__ void gemm_tile(
    char* smraw,
    const float* At, int ldaT, const float* Bm, int N, int K,
    const float* bias, const float* rowS, const float* colV,
    float* Crow, int ldC, int splitCol, float* CtrT, int ldT,
    int doRelu, int row0, int col0)
{
    float* Asf = (float*)smraw;
    float* Bsf = (float*)(smraw + 8704);
    uint32_t sb = (uint32_t)__cvta_generic_to_shared(smraw);

    int tid = threadIdx.x;
    int l = tid & 31, w = tid >> 5;
    int wm = w >> 2, wn = w & 3;          // 2(m) x 4(n) warps: 32x16 each
    int rg = l >> 2, cg = l & 3;          // thread: 4 rows x 4 cols
    int lk = tid >> 4, lseg = (tid & 15) << 2;

    const float* Ab = At + row0 + lseg;
    const float* Bb = Bm + col0 + lseg;

    u64 acc[4][2];
    #pragma unroll
    for (int i = 0; i < 4; i++) { acc[i][0] = 0ull; acc[i][1] = 0ull; }

    // prologue: chunk 0
    cpacg(sb + (uint32_t)((lk * 68 + lseg) << 2),        Ab + (size_t)lk * ldaT);
    cpacg(sb + 8704u + (uint32_t)((lk * 64 + lseg) << 2), Bb + (size_t)lk * N);
    asm volatile("cp.async.commit_group;");

    int nch = K >> 4;
    int mrow = wm * 32 + rg * 4, nc0 = wn * 16 + cg * 4;
    for (int ch = 0; ch < nch; ch++) {
        asm volatile("cp.async.wait_group 0;");
        __syncthreads();
        int buf = ch & 1, nb = buf ^ 1;
        if (ch + 1 < nch) {
            int kc = (ch + 1) << 4;
            cpacg(sb + (uint32_t)(((nb * 1088) + lk * 68 + lseg) << 2),
                  Ab + (size_t)(kc + lk) * ldaT);
            cpacg(sb + 8704u + (uint32_t)(((nb * 1024) + lk * 64 + lseg) << 2),
                  Bb + (size_t)(kc + lk) * N);
            asm volatile("cp.async.commit_group;");
        }
        #pragma unroll
        for (int k = 0; k < 16; k++) {
            float4 av = *(float4*)&Asf[buf * 1088 + k * 68 + mrow];
            ulonglong2 bq = *(ulonglong2*)&Bsf[buf * 1024 + k * 64 + nc0];
            u64 a0, a1, a2, a3;
            PACKDUP(a0, av.x); PACKDUP(a1, av.y); PACKDUP(a2, av.z); PACKDUP(a3, av.w);
            FMA2(acc[0][0], a0, bq.x); FMA2(acc[0][1], a0, bq.y);
            FMA2(acc[1][0], a1, bq.x); FMA2(acc[1][1], a1, bq.y);
            FMA2(acc[2][0], a2, bq.x); FMA2(acc[2][1], a2, bq.y);
            FMA2(acc[3][0], a3, bq.x); FMA2(acc[3][1], a3, bq.y);
        }
    }
    __syncthreads();   // smem reused by next tile

    // epilogue
    int c0 = col0 + nc0;
    float vv[4][4];
    #pragma unroll
    for (int i = 0; i < 4; i++) {
        UNPACK2(vv[i][0], vv[i][1], acc[i][0]);
        UNPACK2(vv[i][2], vv[i][3], acc[i][1]);
    }
    float bj[4], cvj[4];
    #pragma unroll
    for (int j = 0; j < 4; j++) {
        bj[j]  = bias ? __ldcg(bias + c0 + j) : 0.f;
        cvj[j] = rowS ? __ldcg(colV + c0 + j) : 0.f;
    }
    #pragma unroll
    for (int i = 0; i < 4; i++) {
        int r = row0 + mrow + i;
        float rs = rowS ? __ldcg(rowS + r) : 0.f;
        #pragma unroll
        for (int j = 0; j < 4; j++) {
            float v = vv[i][j] + bj[j] + rs * cvj[j];
            if (doRelu) v = fmaxf(v, 0.f);
            vv[i][j] = v;
        }
    }
    if (col0 < splitCol) {
        #pragma unroll
        for (int i = 0; i < 4; i++) {
            float4 o = {vv[i][0], vv[i][1], vv[i][2], vv[i][3]};
            *(float4*)(Crow + (size_t)(row0 + mrow + i) * ldC + c0) = o;
        }
    } else {
        int rb = row0 + mrow;
        #pragma unroll
        for (int j = 0; j < 4; j++) {
            float4 o = {vv[0][j], vv[1][j], vv[2][j], vv[3][j]};
            *(float4*)(CtrT + (size_t)(c0 + j - splitCol) * ldT + rb) = o;
        }
    }
}

// ---------------- the persistent mega-kernel -----------------------------------
#define IT 8
__global__ void __launch_bounds__(256, 2)
mega(const float* __restrict__ X, const int* __restrict__ adj,
     const float* __restrict__ pre_W1, const float* __restrict__ pre_b1,
     const float* __restrict__ pre_W2, const float* __restrict__ pre_b2,
     const float* __restrict__ msg_W1, const float* __restrict__ msg_b1,
     const float* __restrict__ msg_W2, const float* __restrict__ msg_b2,
     const float* __restrict__ gru_Wih, const float* __restrict__ gru_Whh,
     const float* __restrict__ gru_bih, const float* __restrict__ gru_bhh,
     const float* __restrict__ ro_W1, const float* __restrict__ ro_b1,
     const float* __restrict__ ro_W2, const float* __restrict__ ro_b2,
     float* __restrict__ out)
{
    __shared__ __align__(16) char smraw[16896];
    int bid = blockIdx.x, tid = threadIdx.x;

    // ---- P0: prep (XT, M2T, Wcat+bcat, bc) ----
    for (int i = bid * 256 + tid; i < 460800; i += G * 256) {
        if (i < 65536) {                           // XT[k][m] = X[m][k]
            int k = i >> 10, m = i & 1023;
            d_XT[i] = X[(size_t)m * Fn + k];
        } else if (i < 131072) {                   // M2T[k][m] = msg_W2[m][k]
            int j = i - 65536;
            int k = j >> 8, m = j & 255;
            d_M2T[j] = msg_W2[(size_t)m * Hn + k];
        } else if (i < 458752) {                   // Wcat[k][n] + bcat
            int j = i - 131072;
            int k = j / NC, n = j % NC;
            float v;
            if (n < 256)      v = msg_W1[(size_t)k * Hn + n];
            else if (n < 512) v = msg_W1[(size_t)(256 + k) * Hn + (n - 256)];
            else              v = gru_Whh[(size_t)k * 768 + (n - 512)];
            d_Wcat[j] = v;
            if (j < NC)
                d_bcat[j] = j < 256 ? msg_b1[j] : (j < 512 ? 0.f : gru_bhh[j - 512]);
        } else {                                   // bc[n] = msg_b2 @ Wih col n
            int n = i - 458752;
            float s = 0.f;
            for (int k = 0; k < Hn; k++)
                s += msg_b2[k] * gru_Wih[(size_t)k * 768 + n];
            d_bc[n] = s;
        }
    }
    gridbar();

    // ---- P1: Wc gemm (48 tiles) + pre-MLP gemm1 (64 tiles) ----
    for (int t = bid; t < 112; t += G) {
        if (t < 48)
            gemm_tile(smraw, d_M2T, Hn, gru_Wih, 768, Hn,
                      nullptr, nullptr, nullptr,
                      d_Wc, 768, 768, nullptr, 0, 0,
                      (t / 12) * 64, (t % 12) * 64);
        else {
            int t2 = t - 48;
            gemm_tile(smraw, d_XT, BN, pre_W1, Hn, Fn,
                      pre_b1, nullptr, nullptr,
                      nullptr, 0, 0, d_tT, BN,
                      1, (t2 / 4) * 64, (t2 % 4) * 64);
        }
    }
    gridbar();

    // ---- P2: gemm2 -> hT (64 tiles) ----
    for (int t = bid; t < 64; t += G)
        gemm_tile(smraw, d_tT, BN, pre_W2, Hn, Hn,
                  pre_b2, nullptr, nullptr,
                  nullptr, 0, 0, d_hT, BN,
                  0, (t / 4) * 64, (t % 4) * 64);
    gridbar();

    for (int it = 0; it < Tn; it++) {
        // ---- P3: fused gemm: [hi+b1|hj]->big2, gh+bhh->ghT (320 tiles) ----
        for (int t = bid; t < 320; t += G)
            gemm_tile(smraw, d_hT, BN, d_Wcat, NC, Hn,
                      d_bcat, nullptr, nullptr,
                      d_big2, 512, 512, d_ghT, BN,
                      0, (t / 20) * 64, (t % 20) * 64);
        gridbar();

        // ---- P4: eagg (128 tiles of 8 rows) ----
        for (int t = bid; t < 128; t += G) {
            int b  = t >> 5;
            int i0 = (t & 31) * IT;
            int h  = tid;
            float (*adjf)[IT] = (float(*)[IT])smraw;

            float hir[IT], acc[IT];
            #pragma unroll
            for (int q = 0; q < IT; q++) {
                adjf[h][q] = (float)adj[((size_t)(b * Nn + i0 + q)) * Nn + h];
                hir[q] = __ldcg(&d_big2[((size_t)(b * Nn + i0 + q)) * 512 + h]);
                acc[q] = 0.f;
            }
            __syncthreads();

            const float* hjb = d_big2 + (size_t)b * Nn * 512 + 256;
            #pragma unroll 2
            for (int j = 0; j < Nn; j++) {
                float hjv = __ldcg(&hjb[(size_t)j * 512 + h]);
                float4 a04 = *(float4*)&adjf[j][0];
                float4 a47 = *(float4*)&adjf[j][4];
                acc[0] += a04.x * fmaxf(hir[0] + hjv, 0.f);
                acc[1] += a04.y * fmaxf(hir[1] + hjv, 0.f);
                acc[2] += a04.z * fmaxf(hir[2] + hjv, 0.f);
                acc[3] += a04.w * fmaxf(hir[3] + hjv, 0.f);
                acc[4] += a47.x * fmaxf(hir[4] + hjv, 0.f);
                acc[5] += a47.y * fmaxf(hir[5] + hjv, 0.f);
                acc[6] += a47.z * fmaxf(hir[6] + hjv, 0.f);
                acc[7] += a47.w * fmaxf(hir[7] + hjv, 0.f);
            }

            #pragma unroll
            for (int q = 0; q < IT; q++)
                d_aT[(size_t)h * BN + b * Nn + i0 + q] = acc[q];

            if (h < IT) {
                float s = 0.f;
                for (int j = 0; j < Nn; j++) s += adjf[j][h];
                d_deg[b * Nn + i0 + h] = s;
            }
            __syncthreads();   // smem reused by next tile / next phase
        }
        gridbar();

        // ---- P5: gi gemm -> giT (192 tiles) ----
        for (int t = bid; t < 192; t += G)
            gemm_tile(smraw, d_aT, BN, d_Wc, 768, Hn,
                      gru_bih, d_deg, d_bc,
                      nullptr, 0, 0, d_giT, BN,
                      0, (t / 12) * 64, (t % 12) * 64);
        gridbar();

        // ---- P6: GRU elementwise -> hT ----
        for (int id = bid * 256 + tid; id < Hn * BN; id += G * 256) {
            int m = id & 1023, c = id >> 10;
            float ir = __ldcg(&d_giT[(size_t)c * BN + m]);
            float iz = __ldcg(&d_giT[(size_t)(c + 256) * BN + m]);
            float in = __ldcg(&d_giT[(size_t)(c + 512) * BN + m]);
            float hr = __ldcg(&d_ghT[(size_t)c * BN + m]);
            float hz = __ldcg(&d_ghT[(size_t)(c + 256) * BN + m]);
            float hn = __ldcg(&d_ghT[(size_t)(c + 512) * BN + m]);
            float r = 1.f / (1.f + __expf(-(ir + hr)));
            float z = 1.f / (1.f + __expf(-(iz + hz)));
            float n = tanhf(in + r * hn);
            float hv = __ldcg(&d_hT[id]);
            d_hT[id] = (1.f - z) * n + z * hv;
        }
        gridbar();
    }

    // ---- P7: readout (blocks 0..3) ----
    if (bid < Bn) {
        float* gsh = (float*)smraw;
        float* hsh = (float*)(smraw + 1024);
        int b = bid, t = tid;

        float s = 0.f;
        const float* hrow = d_hT + (size_t)t * BN + b * Nn;
        #pragma unroll 4
        for (int i = 0; i < Nn; i++) s += __ldcg(hrow + i);
        gsh[t] = s;
        __syncthreads();

        float s2 = ro_b1[t];
        for (int k = 0; k < Hn; k++) s2 += gsh[k] * ro_W1[(size_t)k * Hn + t];
        hsh[t] = fmaxf(s2, 0.f);
        __syncthreads();

        if (t < An) {
            float s3 = ro_b2[t];
            for (int k = 0; k < Hn; k++) s3 += hsh[k] * ro_W2[(size_t)k * An + t];
            out[b * An + t] = s3;
        }
    }
}

// ---------------- host launch ---------------------------------------------------
extern "C" void kernel_launch(void* const* d_in, const int* in_sizes, int n_in,
                              void* d_out, int out_size)
{
    mega<<<G, 256>>>((const float*)d_in[0], (const int*)d_in[1],
                     (const float*)d_in[2], (const float*)d_in[3],
                     (const float*)d_in[4], (const float*)d_in[5],
                     (const float*)d_in[6], (const float*)d_in[7],
                     (const float*)d_in[8], (const float*)d_in[9],
                     (const float*)d_in[10], (const float*)d_in[11],
                     (const float*)d_in[12], (const float*)d_in[13],
                     (const float*)d_in[14], (const float*)d_in[15],
                     (const float*)d_in[16], (const float*)d_in[17],
                     (float*)d_out);
}